// round 12
// baseline (speedup 1.0000x reference)
#include <cuda_runtime.h>
#include <cuda_bf16.h>
#include <cstdint>
#include <math.h>

// ---------------- problem constants ----------------
#define DIMN     64
#define L_DIM    2016
#define DD       2017
#define DDP      2032
#define BB       512
#define HID      512

#define POFF 0
#define LOFF 2097152
#define NOFF 4194304
#define WOFF 4227072
#define SOFF 6324224

typedef unsigned long long ull;

__device__ __forceinline__ ull pack2(float x, float y) {
    ull r; asm("mov.b64 %0,{%1,%2};" : "=l"(r) : "f"(x), "f"(y)); return r;
}
__device__ __forceinline__ void unpack2(ull v, float& x, float& y) {
    asm("mov.b64 {%0,%1},%2;" : "=f"(x), "=f"(y) : "l"(v));
}
__device__ __forceinline__ ull ffma2(ull a, ull b, ull c) {
    ull d; asm("fma.rn.f32x2 %0,%1,%2,%3;" : "=l"(d) : "l"(a), "l"(b), "l"(c)); return d;
}
__device__ __forceinline__ float ex2f(float x) {
    float y; asm("ex2.approx.f32 %0,%1;" : "=f"(y) : "f"(x)); return y;
}
__device__ __forceinline__ float lg2f(float x) {
    float y; asm("lg2.approx.f32 %0,%1;" : "=f"(y) : "f"(x)); return y;
}
__device__ __forceinline__ uint32_t smem_u32(const void* p) {
    uint32_t a;
    asm("{ .reg .u64 t; cvta.to.shared.u64 t, %1; cvt.u32.u64 %0, t; }" : "=r"(a) : "l"(p));
    return a;
}
#define SW128(o) ((o) ^ (((o) >> 3) & 0x70))

__device__ __forceinline__ void mma16816(float* c, const uint32_t* a, const uint32_t* b) {
    asm volatile(
        "mma.sync.aligned.m16n8k16.row.col.f32.bf16.bf16.f32 "
        "{%0,%1,%2,%3}, {%4,%5,%6,%7}, {%8,%9}, {%0,%1,%2,%3};"
        : "+f"(c[0]), "+f"(c[1]), "+f"(c[2]), "+f"(c[3])
        : "r"(a[0]), "r"(a[1]), "r"(a[2]), "r"(a[3]), "r"(b[0]), "r"(b[1]));
}
__device__ __forceinline__ void ldsm_x4(uint32_t* r, uint32_t addr) {
    asm volatile("ldmatrix.sync.aligned.m8n8.x4.shared.b16 {%0,%1,%2,%3}, [%4];"
                 : "=r"(r[0]), "=r"(r[1]), "=r"(r[2]), "=r"(r[3]) : "r"(addr));
}
__device__ __forceinline__ void ldsm_x2(uint32_t* r, uint32_t addr) {
    asm volatile("ldmatrix.sync.aligned.m8n8.x2.shared.b16 {%0,%1}, [%2];"
                 : "=r"(r[0]), "=r"(r[1]) : "r"(addr));
}
__device__ __forceinline__ void split_bf16(float x, unsigned short& h, unsigned short& l) {
    __nv_bfloat16 hb = __float2bfloat16_rn(x);
    float r = x - __bfloat162float(hb);
    __nv_bfloat16 lb = __float2bfloat16_rn(r);
    h = __bfloat16_as_ushort(hb);
    l = __bfloat16_as_ushort(lb);
}

// ---------------- device scratch ----------------
__device__ float g_flb[BB * DDP];
__device__ float g_part[16 * 262144];
__device__ float g_h1[BB * HID];
__device__ float g_wnoise[BB];
__device__ float g_probe[4194304];
__device__ __nv_bfloat16 g_h2hi[BB * HID], g_h2lo[BB * HID];
__device__ __nv_bfloat16 g_Bhi[4096 * 512], g_Blo[4096 * 512];    // W3^T split [n][k]
__device__ __nv_bfloat16 g_zhi[512 * 64], g_zlo[512 * 64];
__device__ __nv_bfloat16 g_Cthi[BB * 4096], g_Ctlo[BB * 4096];    // B[n][j]=M[c_n][c_j]

// ---------------- kernel: full_l_batch (padded), noises, L ----------------
__global__ void k_prep(const float* __restrict__ Lp, const float* __restrict__ epsL,
                       float* __restrict__ out) {
    int b = blockIdx.x, tid = threadIdx.x;
    __shared__ float flb[DD];
    for (int d = tid; d < DDP; d += 256) {
        float v = 0.0f;
        if (d < DD) {
            float mean = Lp[d];
            float raw  = Lp[DD + d];
            v = mean + expf(tanhf(raw * 0.1f) * 10.0f) * epsL[(size_t)b * DD + d];
            flb[d] = v;
        }
        g_flb[(size_t)b * DDP + d] = v;
    }
    __syncthreads();
    if (tid == 0) g_wnoise[b] = flb[L_DIM];
    if (tid < DIMN) out[NOFF + b * DIMN + tid] = flb[L_DIM];
    for (int idx = tid; idx < 4096; idx += 256) {
        int jr = idx >> 6, ic = idx & 63;
        float v = 0.0f;
        if (ic < jr) v = flb[ic * 63 - (ic * (ic - 1)) / 2 + (jr - ic - 1)];
        out[LOFF + (size_t)b * 4096 + idx] = v;
    }
}

// ---- fp32 SGEMM (FFMA2), 128x64 tile, BK=16, split-K ----
__global__ void __launch_bounds__(256) sgemm(int which, const float* __restrict__ Bm,
                                             int N, int Kb, int kChunk, int lda, int KpadT) {
    const float* __restrict__ A = (which == 0) ? g_flb : g_h1;
    int n0 = blockIdx.x * 64, m0 = blockIdx.y * 128, s = blockIdx.z;
    int k0 = s * kChunk;
    int k1 = min(KpadT, k0 + kChunk);
    __shared__ __align__(16) float As[16][132];
    __shared__ __align__(16) float Bs[16][64];
    int tid = threadIdx.x, tx = tid & 15, ty = tid >> 4;
    ull acc2[4][4];
    #pragma unroll
    for (int p = 0; p < 4; p++)
        #pragma unroll
        for (int j = 0; j < 4; j++) acc2[p][j] = 0ull;

    int ar0 = tid >> 2, ak = (tid & 3) * 4;
    int bk = tid >> 4, bn = (tid & 15) * 4;

    float4 pa0, pa1, pb;
    auto fetch = [&](int kb) {
        int kk = kb + ak;
        pa0 = *(const float4*)&A[(size_t)(m0 + ar0) * lda + kk];
        pa1 = *(const float4*)&A[(size_t)(m0 + ar0 + 64) * lda + kk];
        pb = make_float4(0.f, 0.f, 0.f, 0.f);
        if (kb + bk < Kb) pb = *(const float4*)&Bm[(size_t)(kb + bk) * N + n0 + bn];
    };

    fetch(k0);
    for (int kb = k0; kb < k1; kb += 16) {
        As[ak + 0][ar0] = pa0.x; As[ak + 1][ar0] = pa0.y;
        As[ak + 2][ar0] = pa0.z; As[ak + 3][ar0] = pa0.w;
        As[ak + 0][ar0 + 64] = pa1.x; As[ak + 1][ar0 + 64] = pa1.y;
        As[ak + 2][ar0 + 64] = pa1.z; As[ak + 3][ar0 + 64] = pa1.w;
        *(float4*)&Bs[bk][bn] = pb;
        __syncthreads();
        if (kb + 16 < k1) fetch(kb + 16);
        #pragma unroll
        for (int kk = 0; kk < 16; kk++) {
            ulonglong2 aA = *(const ulonglong2*)&As[kk][ty * 8];
            ulonglong2 aB = *(const ulonglong2*)&As[kk][ty * 8 + 4];
            float4 b = *(const float4*)&Bs[kk][tx * 4];
            ull bp0 = pack2(b.x, b.x), bp1 = pack2(b.y, b.y);
            ull bp2 = pack2(b.z, b.z), bp3 = pack2(b.w, b.w);
            acc2[0][0] = ffma2(aA.x, bp0, acc2[0][0]);
            acc2[0][1] = ffma2(aA.x, bp1, acc2[0][1]);
            acc2[0][2] = ffma2(aA.x, bp2, acc2[0][2]);
            acc2[0][3] = ffma2(aA.x, bp3, acc2[0][3]);
            acc2[1][0] = ffma2(aA.y, bp0, acc2[1][0]);
            acc2[1][1] = ffma2(aA.y, bp1, acc2[1][1]);
            acc2[1][2] = ffma2(aA.y, bp2, acc2[1][2]);
            acc2[1][3] = ffma2(aA.y, bp3, acc2[1][3]);
            acc2[2][0] = ffma2(aB.x, bp0, acc2[2][0]);
            acc2[2][1] = ffma2(aB.x, bp1, acc2[2][1]);
            acc2[2][2] = ffma2(aB.x, bp2, acc2[2][2]);
            acc2[2][3] = ffma2(aB.x, bp3, acc2[2][3]);
            acc2[3][0] = ffma2(aB.y, bp0, acc2[3][0]);
            acc2[3][1] = ffma2(aB.y, bp1, acc2[3][1]);
            acc2[3][2] = ffma2(aB.y, bp2, acc2[3][2]);
            acc2[3][3] = ffma2(aB.y, bp3, acc2[3][3]);
        }
        __syncthreads();
    }
    size_t MN = (size_t)512 * N;
    float* dst = &g_part[(size_t)s * MN];
    #pragma unroll
    for (int p = 0; p < 4; p++) {
        float lo[4], hi[4];
        #pragma unroll
        for (int j = 0; j < 4; j++) unpack2(acc2[p][j], lo[j], hi[j]);
        int m = m0 + ty * 8 + 2 * p;
        *(float4*)&dst[(size_t)m * N + n0 + tx * 4] = make_float4(lo[0], lo[1], lo[2], lo[3]);
        *(float4*)&dst[(size_t)(m + 1) * N + n0 + tx * 4] = make_float4(hi[0], hi[1], hi[2], hi[3]);
    }
}

// ---------------- epilogue: sum 16 partials + bias + gelu ----------------
__global__ void k_epi_gelu(int dst, const float* __restrict__ bias) {
    int idx = blockIdx.x * 256 + threadIdx.x;
    float x = bias[idx & 511];
    #pragma unroll
    for (int s = 0; s < 16; s++) x += g_part[s * 262144 + idx];
    float x3 = x * x * x;
    float t = tanhf(0.7978845608028654f * (x + 0.044715f * x3));
    float v = 0.5f * x * (1.0f + t);
    if (dst == 0) {
        g_h1[idx] = v;
    } else {
        unsigned short h, l;
        split_bf16(v, h, l);
        *(unsigned short*)&g_h2hi[idx] = h;
        *(unsigned short*)&g_h2lo[idx] = l;
    }
}

// ---- z -> bf16 hi/lo ----
__global__ void k_cvt_z(const float* __restrict__ z) {
    int i = (blockIdx.x * 256 + threadIdx.x) * 4;
    float4 x = *(const float4*)&z[i];
    unsigned short h0, h1, h2v, h3, l0, l1, l2, l3;
    split_bf16(x.x, h0, l0); split_bf16(x.y, h1, l1);
    split_bf16(x.z, h2v, l2); split_bf16(x.w, h3, l3);
    *(uint2*)&g_zhi[i] = make_uint2((uint32_t)h1 << 16 | h0, (uint32_t)h3 << 16 | h2v);
    *(uint2*)&g_zlo[i] = make_uint2((uint32_t)l1 << 16 | l0, (uint32_t)l3 << 16 | l2);
}

// ---- W3[k][n] -> g_Bhi/lo [n][k] bf16 split ----
__global__ void __launch_bounds__(256) k_cvt_w3(const float* __restrict__ W3) {
    int n0 = blockIdx.x * 64, k0 = blockIdx.y * 64, tid = threadIdx.x;
    __shared__ float t[64][65];
    #pragma unroll
    for (int i = 0; i < 16; i++) {
        int slot = tid + i * 256;
        int r = slot >> 6, c = slot & 63;
        t[r][c] = W3[(size_t)(k0 + r) * 4096 + n0 + c];
    }
    __syncthreads();
    #pragma unroll
    for (int i = 0; i < 8; i++) {
        int slot = tid + i * 256;
        int r2 = slot >> 5, j = slot & 31;
        unsigned short ha, hb, la, lb;
        split_bf16(t[2 * j][r2], ha, la);
        split_bf16(t[2 * j + 1][r2], hb, lb);
        size_t o = (size_t)(n0 + r2) * 512 + k0 + 2 * j;
        *(uint32_t*)&g_Bhi[o] = (uint32_t)hb << 16 | ha;
        *(uint32_t*)&g_Blo[o] = (uint32_t)lb << 16 | la;
    }
}

// ---- logits via mma.sync: D[512,4096] = h2 @ W3, 3-term bf16 split (R9, proven) ----
#define LA_H 0
#define LA_L 16384
#define LB_H 32768
#define LB_L 49152

__global__ void __launch_bounds__(256) k_logits_mma() {
    extern __shared__ char sm[];
    uint32_t sb = smem_u32(sm);
    int tid = threadIdx.x, w = tid >> 5, lane = tid & 31;
    int n0 = blockIdx.x * 128, m0 = blockIdx.y * 128;
    int wm = (w & 3) * 32, wn = (w >> 2) * 64;

    float acc[2][8][4];
    #pragma unroll
    for (int mt = 0; mt < 2; mt++)
        #pragma unroll
        for (int j = 0; j < 8; j++)
            #pragma unroll
            for (int q = 0; q < 4; q++) acc[mt][j][q] = 0.0f;

    int arow = lane & 15, akq = (lane >> 4) * 8;
    int brow = lane & 7, bkq = ((lane >> 3) & 1) * 8;

    for (int c = 0; c < 8; c++) {
        for (int s = tid; s < 1024; s += 256) {
            int r = s >> 3, q = s & 7;
            uint32_t so = SW128((uint32_t)(r * 128 + q * 16));
            size_t ga = (size_t)(m0 + r) * 512 + c * 64 + q * 8;
            size_t gb = (size_t)(n0 + r) * 512 + c * 64 + q * 8;
            *(uint4*)(sm + LA_H + so) = *(const uint4*)&g_h2hi[ga];
            *(uint4*)(sm + LA_L + so) = *(const uint4*)&g_h2lo[ga];
            *(uint4*)(sm + LB_H + so) = *(const uint4*)&g_Bhi[gb];
            *(uint4*)(sm + LB_L + so) = *(const uint4*)&g_Blo[gb];
        }
        __syncthreads();
        #pragma unroll
        for (int ks = 0; ks < 4; ks++) {
            uint32_t ah[2][4], al[2][4];
            #pragma unroll
            for (int mt = 0; mt < 2; mt++) {
                uint32_t ao = SW128((uint32_t)((wm + mt * 16 + arow) * 128
                                               + (ks * 16 + akq) * 2));
                ldsm_x4(ah[mt], sb + LA_H + ao);
                ldsm_x4(al[mt], sb + LA_L + ao);
            }
            #pragma unroll
            for (int j = 0; j < 8; j++) {
                uint32_t bh[2], bl[2];
                uint32_t bo = SW128((uint32_t)((wn + j * 8 + brow) * 128
                                               + (ks * 16 + bkq) * 2));
                ldsm_x2(bh, sb + LB_H + bo);
                ldsm_x2(bl, sb + LB_L + bo);
                #pragma unroll
                for (int mt = 0; mt < 2; mt++) {
                    mma16816(acc[mt][j], ah[mt], bh);
                    mma16816(acc[mt][j], ah[mt], bl);
                    mma16816(acc[mt][j], al[mt], bh);
                }
            }
        }
        __syncthreads();
    }
    #pragma unroll
    for (int mt = 0; mt < 2; mt++)
        #pragma unroll
        for (int j = 0; j < 8; j++) {
            int r = m0 + wm + mt * 16 + (lane >> 2);
            int cc = n0 + wn + j * 8 + (lane & 3) * 2;
            *(float2*)&g_part[(size_t)r * 4096 + cc] = make_float2(acc[mt][j][0], acc[mt][j][1]);
            *(float2*)&g_part[(size_t)(r + 8) * 4096 + cc] = make_float2(acc[mt][j][2], acc[mt][j][3]);
        }
}

// ---- samples v3: 256-row blocks, warp M=32, 3-term HMMA + Sherman-Morrison ----
#define ZH_OFF 0
#define ZL_OFF 32768
#define CH_OFF 65536
#define CL_OFF 73728

__device__ __forceinline__ void samples_mma_body(int blk, const int* __restrict__ tg,
                                                 float* __restrict__ outp, bool toOut) {
    extern __shared__ char sm[];
    uint32_t sb = smem_u32(sm);
    __shared__ int tgs[256];
    __shared__ float wsh;
    int b = blk >> 1, i0 = (blk & 1) * 256;
    int tid = threadIdx.x, w = tid >> 5, lane = tid & 31;

    for (int slot = tid; slot < 2048; slot += 256) {
        int r = slot >> 3, q = slot & 7;
        uint32_t so = SW128((uint32_t)(r * 128 + q * 16));
        *(uint4*)(sm + ZH_OFF + so) = *(const uint4*)&g_zhi[(size_t)(i0 + r) * 64 + q * 8];
        *(uint4*)(sm + ZL_OFF + so) = *(const uint4*)&g_zlo[(size_t)(i0 + r) * 64 + q * 8];
    }
    for (int slot = tid; slot < 512; slot += 256) {
        int r = slot >> 3, q = slot & 7;
        uint32_t so = SW128((uint32_t)(r * 128 + q * 16));
        *(uint4*)(sm + CH_OFF + so) = *(const uint4*)&g_Cthi[(size_t)b * 4096 + r * 64 + q * 8];
        *(uint4*)(sm + CL_OFF + so) = *(const uint4*)&g_Ctlo[(size_t)b * 4096 + r * 64 + q * 8];
    }
    if (tid < 256) tgs[tid] = tg[i0 + tid];
    if (tid == 0) wsh = g_wnoise[b];
    __syncthreads();

    float acc[2][8][4];
    #pragma unroll
    for (int mt = 0; mt < 2; mt++)
        #pragma unroll
        for (int j = 0; j < 8; j++)
            #pragma unroll
            for (int q = 0; q < 4; q++) acc[mt][j][q] = 0.0f;

    int wm = w * 32;
    int arow = lane & 15, akq = (lane >> 4) * 8;
    int brow = lane & 7, bkq = ((lane >> 3) & 1) * 8;

    #pragma unroll
    for (int ks = 0; ks < 4; ks++) {
        uint32_t ah[2][4], al[2][4];
        #pragma unroll
        for (int mt = 0; mt < 2; mt++) {
            uint32_t ao = SW128((uint32_t)((wm + mt * 16 + arow) * 128
                                           + (ks * 16 + akq) * 2));
            ldsm_x4(ah[mt], sb + ZH_OFF + ao);
            ldsm_x4(al[mt], sb + ZL_OFF + ao);
        }
        #pragma unroll
        for (int j = 0; j < 8; j++) {
            uint32_t bh[2], bl[2];
            uint32_t bo = SW128((uint32_t)((j * 8 + brow) * 128 + (ks * 16 + bkq) * 2));
            ldsm_x2(bh, sb + CH_OFF + bo);
            ldsm_x2(bl, sb + CL_OFF + bo);
            #pragma unroll
            for (int mt = 0; mt < 2; mt++) {
                mma16816(acc[mt][j], ah[mt], bh);
                mma16816(acc[mt][j], ah[mt], bl);
                mma16816(acc[mt][j], al[mt], bh);
            }
        }
    }
    __syncthreads();
    float* s0 = (float*)sm;   // reuse Z area: [256][64] f32 (65536 bytes = ZH+ZL)
    #pragma unroll
    for (int mt = 0; mt < 2; mt++)
        #pragma unroll
        for (int j = 0; j < 8; j++) {
            int r0w = wm + mt * 16 + (lane >> 2), c0 = j * 8 + (lane & 3) * 2;
            s0[r0w * 64 + c0] = acc[mt][j][0];
            s0[r0w * 64 + c0 + 1] = acc[mt][j][1];
            s0[(r0w + 8) * 64 + c0] = acc[mt][j][2];
            s0[(r0w + 8) * 64 + c0 + 1] = acc[mt][j][3];
        }
    __syncthreads();
    float wn = wsh;
    int tx = tid & 15, ty = tid >> 4;
    #pragma unroll
    for (int rr = 0; rr < 16; rr++) {
        int mr = ty * 16 + rr;
        int t = tgs[mr];
        int trow = (t < 64) ? t : 63;
        float corr = (t < 64) ? (wn * s0[mr * 64 + trow]) : 0.0f;
        float4 s0v = *(const float4*)&s0[mr * 64 + tx * 4];
        float cv[4];
        #pragma unroll
        for (int q = 0; q < 4; q++) {
            uint32_t co = SW128((uint32_t)((tx * 4 + q) * 128 + trow * 2));
            float ch = __bfloat162float(*(const __nv_bfloat16*)(sm + CH_OFF + co));
            float cl = __bfloat162float(*(const __nv_bfloat16*)(sm + CL_OFF + co));
            cv[q] = ch + cl;
        }
        float4 o;
        o.x = wn * s0v.x - cv[0] * corr;
        o.y = wn * s0v.y - cv[1] * corr;
        o.z = wn * s0v.z - cv[2] * corr;
        o.w = wn * s0v.w - cv[3] * corr;
        int nb = tx * 4;
        if (t == nb + 0) o.x = 0.0f;
        if (t == nb + 1) o.y = 0.0f;
        if (t == nb + 2) o.z = 0.0f;
        if (t == nb + 3) o.w = 0.0f;
        size_t off = toOut ? (SOFF + ((size_t)b * 512 + i0 + mr) * 64 + nb)
                           : ((size_t)blk * 16384 + mr * 64 + nb);
        *(float4*)&outp[off] = o;
    }
}

__global__ void __launch_bounds__(256) k_samples_probe(const int* __restrict__ tg) {
    samples_mma_body(blockIdx.x, tg, g_probe, false);
}
__global__ void __launch_bounds__(256) k_samples_mma(const int* __restrict__ tg,
                                                     float* __restrict__ out) {
    samples_mma_body(blockIdx.x, tg, out, true);
}

// ---- fused: logits epilogue + gumbel + 20x sinkhorn (log2) + greedy + backsub ----
__global__ void __launch_bounds__(256) k_sinkgreedy(const float* __restrict__ b3,
                                                    const float* __restrict__ gum,
                                                    float* __restrict__ out) {
    extern __shared__ float dsm[];
    float* m   = dsm;
    float* Lsh = dsm + 64 * 65;
    float* Msh = dsm + 2 * 64 * 65;
    __shared__ int colsh[64];
    int b = blockIdx.x, tid = threadIdx.x, lane = tid & 31, wd = tid >> 5;

    const float* Lg = out + LOFF + (size_t)b * 4096;
    for (int idx = tid; idx < 4096; idx += 256) {
        float x = g_part[(size_t)b * 4096 + idx] + b3[idx];
        x = tanhf(x * 0.1f) * 10.0f;
        float u = gum[(size_t)b * 4096 + idx];
        u = fmaxf(u, 1e-8f);
        float g = -__logf(-__logf(u));
        m[(idx >> 6) * 65 + (idx & 63)] = (x + g) * 7.213475204444817f;
        Lsh[(idx >> 6) * 65 + (idx & 63)] = Lg[idx];
    }
    __syncthreads();

    int r0 = wd * 8;
    float a[8], c[8], sm2[8];
    for (int it = 0; it < 20; it++) {
        #pragma unroll
        for (int q = 0; q < 8; q++) {
            a[q] = m[(r0 + q) * 65 + lane];
            c[q] = m[(r0 + q) * 65 + 32 + lane];
        }
        if (it == 0) {
            float mx[8];
            #pragma unroll
            for (int q = 0; q < 8; q++) mx[q] = fmaxf(a[q], c[q]);
            #pragma unroll
            for (int off = 16; off; off >>= 1)
                #pragma unroll
                for (int q = 0; q < 8; q++) mx[q] = fmaxf(mx[q], __shfl_xor_sync(~0u, mx[q], off));
            #pragma unroll
            for (int q = 0; q < 8; q++) sm2[q] = ex2f(a[q] - mx[q]) + ex2f(c[q] - mx[q]);
            #pragma unroll
            for (int off = 16; off; off >>= 1)
                #pragma unroll
                for (int q = 0; q < 8; q++) sm2[q] += __shfl_xor_sync(~0u, sm2[q], off);
            #pragma unroll
            for (int q = 0; q < 8; q++) {
                float lse = mx[q] + lg2f(sm2[q]);
                a[q] -= lse; c[q] -= lse;
            }
        } else {
            #pragma unroll
            for (int q = 0; q < 8; q++) sm2[q] = ex2f(a[q]) + ex2f(c[q]);
            #pragma unroll
            for (int off = 16; off; off >>= 1)
                #pragma unroll
                for (int q = 0; q < 8; q++) sm2[q] += __shfl_xor_sync(~0u, sm2[q], off);
            #pragma unroll
            for (int q = 0; q < 8; q++) {
                float lse = lg2f(sm2[q]);
                a[q] -= lse; c[q] -= lse;
            }
        }
        #pragma unroll
        for (int q = 0; q < 8; q++) {
            m[(r0 + q) * 65 + lane] = a[q];
            m[(r0 + q) * 65 + 32 + lane] = c[q];
        }
        __syncthreads();
        #pragma unroll
        for (int q = 0; q < 8; q++) {
            a[q] = m[lane * 65 + r0 + q];
            c[q] = m[(lane + 32) * 65 + r0 + q];
        }
        #pragma unroll
        for (int q = 0; q < 8; q++) sm2[q] = ex2f(a[q]) + ex2f(c[q]);
        #pragma unroll
        for (int off = 16; off; off >>= 1)
            #pragma unroll
            for (int q = 0; q < 8; q++) sm2[q] += __shfl_xor_sync(~0u, sm2[q], off);
        #pragma unroll
        for (int q = 0; q < 8; q++) {
            float lse = lg2f(sm2[q]);
            m[lane * 65 + r0 + q] = a[q] - lse;
            m[(lane + 32) * 65 + r0 + q] = c[q] - lse;
        }
        __syncthreads();
    }

    if (tid >= 224) {
        bool av0 = true, av1 = true;
        for (int i = 0; i < 64; i++) {
            float v0 = av0 ? m[i * 65 + lane] : -1e30f;
            float v1 = av1 ? m[i * 65 + 32 + lane] : -1e30f;
            float bv = v0; int bi = lane;
            if (v1 > v0) { bv = v1; bi = lane + 32; }
            #pragma unroll
            for (int off = 16; off; off >>= 1) {
                float ov = __shfl_xor_sync(~0u, bv, off);
                int   oi = __shfl_xor_sync(~0u, bi, off);
                if (ov > bv || (ov == bv && oi < bi)) { bv = ov; bi = oi; }
            }
            if (bi == lane) av0 = false;
            if (bi == lane + 32) av1 = false;
            if (lane == 0) colsh[i] = bi;
        }
    } else if (tid < 64) {
        int bc = tid;
        for (int aa = 63; aa >= 0; aa--) {
            float acc0 = (aa == bc) ? 1.0f : 0.0f, acc1 = 0.0f;
            int k = aa + 1;
            for (; k + 1 <= bc; k += 2) {
                acc0 += Lsh[k * 65 + aa] * Msh[k * 65 + bc];
                acc1 += Lsh[(k + 1) * 65 + aa] * Msh[(k + 1) * 65 + bc];
            }
            if (k <= bc) acc0 += Lsh[k * 65 + aa] * Msh[k * 65 + bc];
            Msh[aa * 65 + bc] = acc0 + acc1;
        }
    }
    __syncthreads();
    for (int idx = tid; idx < 4096; idx += 256) {
        int i = idx >> 6, l = idx & 63;
        out[POFF + (size_t)b * 4096 + idx] = (l == colsh[i]) ? 1.0f : 0.0f;
        out[WOFF + (size_t)b * 4096 + idx] = Lsh[colsh[i] * 65 + colsh[l]];
        float v = Msh[colsh[i] * 65 + colsh[l]];
        unsigned short hh, ll;
        split_bf16(v, hh, ll);
        *(unsigned short*)&g_Cthi[(size_t)b * 4096 + idx] = hh;
        *(unsigned short*)&g_Ctlo[(size_t)b * 4096 + idx] = ll;
    }
}

// ---------------- launch ----------------
extern "C" void kernel_launch(void* const* d_in, const int* in_sizes, int n_in,
                              void* d_out, int out_size) {
    const float* Lp  = (const float*)d_in[0];
    const float* eps = (const float*)d_in[1];
    const float* gum = (const float*)d_in[2];
    const float* z   = (const float*)d_in[3];
    const float* W1  = (const float*)d_in[4];
    const float* b1  = (const float*)d_in[5];
    const float* W2  = (const float*)d_in[6];
    const float* b2  = (const float*)d_in[7];
    const float* W3  = (const float*)d_in[8];
    const float* b3  = (const float*)d_in[9];
    const int*   tg  = (const int*)d_in[10];
    float* out = (float*)d_out;

    cudaFuncSetAttribute(k_sinkgreedy, cudaFuncAttributeMaxDynamicSharedMemorySize, 50176);
    cudaFuncSetAttribute(k_samples_mma, cudaFuncAttributeMaxDynamicSharedMemorySize, 81920);
    cudaFuncSetAttribute(k_samples_probe, cudaFuncAttributeMaxDynamicSharedMemorySize, 81920);
    cudaFuncSetAttribute(k_logits_mma, cudaFuncAttributeMaxDynamicSharedMemorySize, 65536);

    k_cvt_z<<<32, 256>>>(z);                                          // 1
    k_prep<<<512, 256>>>(Lp, eps, out);                               // 2
    sgemm<<<dim3(8, 4, 16), 256>>>(0, W1, 512, 2017, 128, DDP, DDP);  // 3
    k_samples_probe<<<256, 256, 81920>>>(tg);                         // 4 <- profiled
    k_epi_gelu<<<1024, 256>>>(0, b1);                                 // 5
    sgemm<<<dim3(8, 4, 16), 256>>>(1, W2, 512, 512, 32, 512, 512);    // 6
    k_epi_gelu<<<1024, 256>>>(1, b2);                                 // 7
    k_cvt_w3<<<dim3(64, 8), 256>>>(W3);                               // 8
    k_logits_mma<<<dim3(32, 4), 256, 65536>>>();                      // 9
    k_sinkgreedy<<<512, 256, 49920>>>(b3, gum, out);                  // 10
    k_samples_mma<<<1024, 256, 81920>>>(tg, out);                     // 11
}

// round 14
// speedup vs baseline: 1.0783x; 1.0783x over previous
#include <cuda_runtime.h>
#include <cuda_bf16.h>
#include <cstdint>
#include <math.h>

// ---------------- problem constants ----------------
#define DIMN     64
#define L_DIM    2016
#define DD       2017
#define DDP      2032
#define BB       512
#define HID      512

#define POFF 0
#define LOFF 2097152
#define NOFF 4194304
#define WOFF 4227072
#define SOFF 6324224

typedef unsigned long long ull;

__device__ __forceinline__ ull pack2(float x, float y) {
    ull r; asm("mov.b64 %0,{%1,%2};" : "=l"(r) : "f"(x), "f"(y)); return r;
}
__device__ __forceinline__ void unpack2(ull v, float& x, float& y) {
    asm("mov.b64 {%0,%1},%2;" : "=f"(x), "=f"(y) : "l"(v));
}
__device__ __forceinline__ ull ffma2(ull a, ull b, ull c) {
    ull d; asm("fma.rn.f32x2 %0,%1,%2,%3;" : "=l"(d) : "l"(a), "l"(b), "l"(c)); return d;
}
__device__ __forceinline__ float ex2f(float x) {
    float y; asm("ex2.approx.f32 %0,%1;" : "=f"(y) : "f"(x)); return y;
}
__device__ __forceinline__ float lg2f(float x) {
    float y; asm("lg2.approx.f32 %0,%1;" : "=f"(y) : "f"(x)); return y;
}
__device__ __forceinline__ uint32_t smem_u32(const void* p) {
    uint32_t a;
    asm("{ .reg .u64 t; cvta.to.shared.u64 t, %1; cvt.u32.u64 %0, t; }" : "=r"(a) : "l"(p));
    return a;
}
#define SW128(o) ((o) ^ (((o) >> 3) & 0x70))

__device__ __forceinline__ void mma16816(float* c, const uint32_t* a, const uint32_t* b) {
    asm volatile(
        "mma.sync.aligned.m16n8k16.row.col.f32.bf16.bf16.f32 "
        "{%0,%1,%2,%3}, {%4,%5,%6,%7}, {%8,%9}, {%0,%1,%2,%3};"
        : "+f"(c[0]), "+f"(c[1]), "+f"(c[2]), "+f"(c[3])
        : "r"(a[0]), "r"(a[1]), "r"(a[2]), "r"(a[3]), "r"(b[0]), "r"(b[1]));
}
__device__ __forceinline__ void ldsm_x4(uint32_t* r, uint32_t addr) {
    asm volatile("ldmatrix.sync.aligned.m8n8.x4.shared.b16 {%0,%1,%2,%3}, [%4];"
                 : "=r"(r[0]), "=r"(r[1]), "=r"(r[2]), "=r"(r[3]) : "r"(addr));
}
__device__ __forceinline__ void ldsm_x2(uint32_t* r, uint32_t addr) {
    asm volatile("ldmatrix.sync.aligned.m8n8.x2.shared.b16 {%0,%1}, [%2];"
                 : "=r"(r[0]), "=r"(r[1]) : "r"(addr));
}
__device__ __forceinline__ void split_bf16(float x, unsigned short& h, unsigned short& l) {
    __nv_bfloat16 hb = __float2bfloat16_rn(x);
    float r = x - __bfloat162float(hb);
    __nv_bfloat16 lb = __float2bfloat16_rn(r);
    h = __bfloat16_as_ushort(hb);
    l = __bfloat16_as_ushort(lb);
}

// ---------------- device scratch ----------------
__device__ float g_flb[BB * DDP];
__device__ float g_part[16 * 262144];
__device__ float g_h1[BB * HID];
__device__ float g_wnoise[BB];
__device__ __nv_bfloat16 g_h2hi[BB * HID], g_h2lo[BB * HID];
__device__ __nv_bfloat16 g_Bhi[4096 * 512], g_Blo[4096 * 512];    // W3^T split [n][k]
__device__ __nv_bfloat16 g_zhi[512 * 64], g_zlo[512 * 64];
__device__ __nv_bfloat16 g_Cthi[BB * 4096], g_Ctlo[BB * 4096];    // B[n][j]=M[c_n][c_j]

// ---------------- kernel: full_l_batch (padded), noises, L ----------------
__global__ void k_prep(const float* __restrict__ Lp, const float* __restrict__ epsL,
                       float* __restrict__ out) {
    int b = blockIdx.x, tid = threadIdx.x;
    __shared__ float flb[DD];
    for (int d = tid; d < DDP; d += 256) {
        float v = 0.0f;
        if (d < DD) {
            float mean = Lp[d];
            float raw  = Lp[DD + d];
            v = mean + expf(tanhf(raw * 0.1f) * 10.0f) * epsL[(size_t)b * DD + d];
            flb[d] = v;
        }
        g_flb[(size_t)b * DDP + d] = v;
    }
    __syncthreads();
    if (tid == 0) g_wnoise[b] = flb[L_DIM];
    if (tid < DIMN) out[NOFF + b * DIMN + tid] = flb[L_DIM];
    for (int idx = tid; idx < 4096; idx += 256) {
        int jr = idx >> 6, ic = idx & 63;
        float v = 0.0f;
        if (ic < jr) v = flb[ic * 63 - (ic * (ic - 1)) / 2 + (jr - ic - 1)];
        out[LOFF + (size_t)b * 4096 + idx] = v;
    }
}

// ---- fp32 SGEMM (FFMA2), 128x64 tile, BK=16, split-K ----
__global__ void __launch_bounds__(256) sgemm(int which, const float* __restrict__ Bm,
                                             int N, int Kb, int kChunk, int lda, int KpadT) {
    const float* __restrict__ A = (which == 0) ? g_flb : g_h1;
    int n0 = blockIdx.x * 64, m0 = blockIdx.y * 128, s = blockIdx.z;
    int k0 = s * kChunk;
    int k1 = min(KpadT, k0 + kChunk);
    __shared__ __align__(16) float As[16][132];
    __shared__ __align__(16) float Bs[16][64];
    int tid = threadIdx.x, tx = tid & 15, ty = tid >> 4;
    ull acc2[4][4];
    #pragma unroll
    for (int p = 0; p < 4; p++)
        #pragma unroll
        for (int j = 0; j < 4; j++) acc2[p][j] = 0ull;

    int ar0 = tid >> 2, ak = (tid & 3) * 4;
    int bk = tid >> 4, bn = (tid & 15) * 4;

    float4 pa0, pa1, pb;
    auto fetch = [&](int kb) {
        int kk = kb + ak;
        pa0 = *(const float4*)&A[(size_t)(m0 + ar0) * lda + kk];
        pa1 = *(const float4*)&A[(size_t)(m0 + ar0 + 64) * lda + kk];
        pb = make_float4(0.f, 0.f, 0.f, 0.f);
        if (kb + bk < Kb) pb = *(const float4*)&Bm[(size_t)(kb + bk) * N + n0 + bn];
    };

    fetch(k0);
    for (int kb = k0; kb < k1; kb += 16) {
        As[ak + 0][ar0] = pa0.x; As[ak + 1][ar0] = pa0.y;
        As[ak + 2][ar0] = pa0.z; As[ak + 3][ar0] = pa0.w;
        As[ak + 0][ar0 + 64] = pa1.x; As[ak + 1][ar0 + 64] = pa1.y;
        As[ak + 2][ar0 + 64] = pa1.z; As[ak + 3][ar0 + 64] = pa1.w;
        *(float4*)&Bs[bk][bn] = pb;
        __syncthreads();
        if (kb + 16 < k1) fetch(kb + 16);
        #pragma unroll
        for (int kk = 0; kk < 16; kk++) {
            ulonglong2 aA = *(const ulonglong2*)&As[kk][ty * 8];
            ulonglong2 aB = *(const ulonglong2*)&As[kk][ty * 8 + 4];
            float4 b = *(const float4*)&Bs[kk][tx * 4];
            ull bp0 = pack2(b.x, b.x), bp1 = pack2(b.y, b.y);
            ull bp2 = pack2(b.z, b.z), bp3 = pack2(b.w, b.w);
            acc2[0][0] = ffma2(aA.x, bp0, acc2[0][0]);
            acc2[0][1] = ffma2(aA.x, bp1, acc2[0][1]);
            acc2[0][2] = ffma2(aA.x, bp2, acc2[0][2]);
            acc2[0][3] = ffma2(aA.x, bp3, acc2[0][3]);
            acc2[1][0] = ffma2(aA.y, bp0, acc2[1][0]);
            acc2[1][1] = ffma2(aA.y, bp1, acc2[1][1]);
            acc2[1][2] = ffma2(aA.y, bp2, acc2[1][2]);
            acc2[1][3] = ffma2(aA.y, bp3, acc2[1][3]);
            acc2[2][0] = ffma2(aB.x, bp0, acc2[2][0]);
            acc2[2][1] = ffma2(aB.x, bp1, acc2[2][1]);
            acc2[2][2] = ffma2(aB.x, bp2, acc2[2][2]);
            acc2[2][3] = ffma2(aB.x, bp3, acc2[2][3]);
            acc2[3][0] = ffma2(aB.y, bp0, acc2[3][0]);
            acc2[3][1] = ffma2(aB.y, bp1, acc2[3][1]);
            acc2[3][2] = ffma2(aB.y, bp2, acc2[3][2]);
            acc2[3][3] = ffma2(aB.y, bp3, acc2[3][3]);
        }
        __syncthreads();
    }
    size_t MN = (size_t)512 * N;
    float* dst = &g_part[(size_t)s * MN];
    #pragma unroll
    for (int p = 0; p < 4; p++) {
        float lo[4], hi[4];
        #pragma unroll
        for (int j = 0; j < 4; j++) unpack2(acc2[p][j], lo[j], hi[j]);
        int m = m0 + ty * 8 + 2 * p;
        *(float4*)&dst[(size_t)m * N + n0 + tx * 4] = make_float4(lo[0], lo[1], lo[2], lo[3]);
        *(float4*)&dst[(size_t)(m + 1) * N + n0 + tx * 4] = make_float4(hi[0], hi[1], hi[2], hi[3]);
    }
}

// ---------------- epilogue: sum 16 partials + bias + gelu ----------------
__global__ void k_epi_gelu(int dst, const float* __restrict__ bias) {
    int idx = blockIdx.x * 256 + threadIdx.x;
    float x = bias[idx & 511];
    #pragma unroll
    for (int s = 0; s < 16; s++) x += g_part[s * 262144 + idx];
    float x3 = x * x * x;
    float t = tanhf(0.7978845608028654f * (x + 0.044715f * x3));
    float v = 0.5f * x * (1.0f + t);
    if (dst == 0) {
        g_h1[idx] = v;
    } else {
        unsigned short h, l;
        split_bf16(v, h, l);
        *(unsigned short*)&g_h2hi[idx] = h;
        *(unsigned short*)&g_h2lo[idx] = l;
    }
}

// ---- z -> bf16 hi/lo ----
__global__ void k_cvt_z(const float* __restrict__ z) {
    int i = (blockIdx.x * 256 + threadIdx.x) * 4;
    float4 x = *(const float4*)&z[i];
    unsigned short h0, h1, h2v, h3, l0, l1, l2, l3;
    split_bf16(x.x, h0, l0); split_bf16(x.y, h1, l1);
    split_bf16(x.z, h2v, l2); split_bf16(x.w, h3, l3);
    *(uint2*)&g_zhi[i] = make_uint2((uint32_t)h1 << 16 | h0, (uint32_t)h3 << 16 | h2v);
    *(uint2*)&g_zlo[i] = make_uint2((uint32_t)l1 << 16 | l0, (uint32_t)l3 << 16 | l2);
}

// ---- W3[k][n] -> g_Bhi/lo [n][k] bf16 split ----
__global__ void __launch_bounds__(256) k_cvt_w3(const float* __restrict__ W3) {
    int n0 = blockIdx.x * 64, k0 = blockIdx.y * 64, tid = threadIdx.x;
    __shared__ float t[64][65];
    #pragma unroll
    for (int i = 0; i < 16; i++) {
        int slot = tid + i * 256;
        int r = slot >> 6, c = slot & 63;
        t[r][c] = W3[(size_t)(k0 + r) * 4096 + n0 + c];
    }
    __syncthreads();
    #pragma unroll
    for (int i = 0; i < 8; i++) {
        int slot = tid + i * 256;
        int r2 = slot >> 5, j = slot & 31;
        unsigned short ha, hb, la, lb;
        split_bf16(t[2 * j][r2], ha, la);
        split_bf16(t[2 * j + 1][r2], hb, lb);
        size_t o = (size_t)(n0 + r2) * 512 + k0 + 2 * j;
        *(uint32_t*)&g_Bhi[o] = (uint32_t)hb << 16 | ha;
        *(uint32_t*)&g_Blo[o] = (uint32_t)lb << 16 | la;
    }
}

// ---- logits via mma.sync: D[512,4096] = h2 @ W3, 3-term bf16 split (proven) ----
#define LA_H 0
#define LA_L 16384
#define LB_H 32768
#define LB_L 49152

__global__ void __launch_bounds__(256) k_logits_mma() {
    extern __shared__ char sm[];
    uint32_t sb = smem_u32(sm);
    int tid = threadIdx.x, w = tid >> 5, lane = tid & 31;
    int n0 = blockIdx.x * 128, m0 = blockIdx.y * 128;
    int wm = (w & 3) * 32, wn = (w >> 2) * 64;

    float acc[2][8][4];
    #pragma unroll
    for (int mt = 0; mt < 2; mt++)
        #pragma unroll
        for (int j = 0; j < 8; j++)
            #pragma unroll
            for (int q = 0; q < 4; q++) acc[mt][j][q] = 0.0f;

    int arow = lane & 15, akq = (lane >> 4) * 8;
    int brow = lane & 7, bkq = ((lane >> 3) & 1) * 8;

    for (int c = 0; c < 8; c++) {
        for (int s = tid; s < 1024; s += 256) {
            int r = s >> 3, q = s & 7;
            uint32_t so = SW128((uint32_t)(r * 128 + q * 16));
            size_t ga = (size_t)(m0 + r) * 512 + c * 64 + q * 8;
            size_t gb = (size_t)(n0 + r) * 512 + c * 64 + q * 8;
            *(uint4*)(sm + LA_H + so) = *(const uint4*)&g_h2hi[ga];
            *(uint4*)(sm + LA_L + so) = *(const uint4*)&g_h2lo[ga];
            *(uint4*)(sm + LB_H + so) = *(const uint4*)&g_Bhi[gb];
            *(uint4*)(sm + LB_L + so) = *(const uint4*)&g_Blo[gb];
        }
        __syncthreads();
        #pragma unroll
        for (int ks = 0; ks < 4; ks++) {
            uint32_t ah[2][4], al[2][4];
            #pragma unroll
            for (int mt = 0; mt < 2; mt++) {
                uint32_t ao = SW128((uint32_t)((wm + mt * 16 + arow) * 128
                                               + (ks * 16 + akq) * 2));
                ldsm_x4(ah[mt], sb + LA_H + ao);
                ldsm_x4(al[mt], sb + LA_L + ao);
            }
            #pragma unroll
            for (int j = 0; j < 8; j++) {
                uint32_t bh[2], bl[2];
                uint32_t bo = SW128((uint32_t)((wn + j * 8 + brow) * 128
                                               + (ks * 16 + bkq) * 2));
                ldsm_x2(bh, sb + LB_H + bo);
                ldsm_x2(bl, sb + LB_L + bo);
                #pragma unroll
                for (int mt = 0; mt < 2; mt++) {
                    mma16816(acc[mt][j], ah[mt], bh);
                    mma16816(acc[mt][j], ah[mt], bl);
                    mma16816(acc[mt][j], al[mt], bh);
                }
            }
        }
        __syncthreads();
    }
    #pragma unroll
    for (int mt = 0; mt < 2; mt++)
        #pragma unroll
        for (int j = 0; j < 8; j++) {
            int r = m0 + wm + mt * 16 + (lane >> 2);
            int cc = n0 + wn + j * 8 + (lane & 3) * 2;
            *(float2*)&g_part[(size_t)r * 4096 + cc] = make_float2(acc[mt][j][0], acc[mt][j][1]);
            *(float2*)&g_part[(size_t)(r + 8) * 4096 + cc] = make_float2(acc[mt][j][2], acc[mt][j][3]);
        }
}

// ---- samples v3 (proven): 256-row blocks, warp M=32, HMMA + Sherman-Morrison ----
#define ZH_OFF 0
#define ZL_OFF 32768
#define CH_OFF 65536
#define CL_OFF 73728

__global__ void __launch_bounds__(256) k_samples_mma(const int* __restrict__ tg,
                                                     float* __restrict__ out) {
    extern __shared__ char sm[];
    uint32_t sb = smem_u32(sm);
    __shared__ int tgs[256];
    __shared__ float wsh;
    int blk = blockIdx.x, b = blk >> 1, i0 = (blk & 1) * 256;
    int tid = threadIdx.x, w = tid >> 5, lane = tid & 31;

    for (int slot = tid; slot < 2048; slot += 256) {
        int r = slot >> 3, q = slot & 7;
        uint32_t so = SW128((uint32_t)(r * 128 + q * 16));
        *(uint4*)(sm + ZH_OFF + so) = *(const uint4*)&g_zhi[(size_t)(i0 + r) * 64 + q * 8];
        *(uint4*)(sm + ZL_OFF + so) = *(const uint4*)&g_zlo[(size_t)(i0 + r) * 64 + q * 8];
    }
    for (int slot = tid; slot < 512; slot += 256) {
        int r = slot >> 3, q = slot & 7;
        uint32_t so = SW128((uint32_t)(r * 128 + q * 16));
        *(uint4*)(sm + CH_OFF + so) = *(const uint4*)&g_Cthi[(size_t)b * 4096 + r * 64 + q * 8];
        *(uint4*)(sm + CL_OFF + so) = *(const uint4*)&g_Ctlo[(size_t)b * 4096 + r * 64 + q * 8];
    }
    if (tid < 256) tgs[tid] = tg[i0 + tid];
    if (tid == 0) wsh = g_wnoise[b];
    __syncthreads();

    float acc[2][8][4];
    #pragma unroll
    for (int mt = 0; mt < 2; mt++)
        #pragma unroll
        for (int j = 0; j < 8; j++)
            #pragma unroll
            for (int q = 0; q < 4; q++) acc[mt][j][q] = 0.0f;

    int wm = w * 32;
    int arow = lane & 15, akq = (lane >> 4) * 8;
    int brow = lane & 7, bkq = ((lane >> 3) & 1) * 8;

    #pragma unroll
    for (int ks = 0; ks < 4; ks++) {
        uint32_t ah[2][4], al[2][4];
        #pragma unroll
        for (int mt = 0; mt < 2; mt++) {
            uint32_t ao = SW128((uint32_t)((wm + mt * 16 + arow) * 128
                                           + (ks * 16 + akq) * 2));
            ldsm_x4(ah[mt], sb + ZH_OFF + ao);
            ldsm_x4(al[mt], sb + ZL_OFF + ao);
        }
        #pragma unroll
        for (int j = 0; j < 8; j++) {
            uint32_t bh[2], bl[2];
            uint32_t bo = SW128((uint32_t)((j * 8 + brow) * 128 + (ks * 16 + bkq) * 2));
            ldsm_x2(bh, sb + CH_OFF + bo);
            ldsm_x2(bl, sb + CL_OFF + bo);
            #pragma unroll
            for (int mt = 0; mt < 2; mt++) {
                mma16816(acc[mt][j], ah[mt], bh);
                mma16816(acc[mt][j], ah[mt], bl);
                mma16816(acc[mt][j], al[mt], bh);
            }
        }
    }
    __syncthreads();
    float* s0 = (float*)sm;   // reuse Z area: [256][64] f32
    #pragma unroll
    for (int mt = 0; mt < 2; mt++)
        #pragma unroll
        for (int j = 0; j < 8; j++) {
            int r0w = wm + mt * 16 + (lane >> 2), c0 = j * 8 + (lane & 3) * 2;
            s0[r0w * 64 + c0] = acc[mt][j][0];
            s0[r0w * 64 + c0 + 1] = acc[mt][j][1];
            s0[(r0w + 8) * 64 + c0] = acc[mt][j][2];
            s0[(r0w + 8) * 64 + c0 + 1] = acc[mt][j][3];
        }
    __syncthreads();
    float wn = wsh;
    int tx = tid & 15, ty = tid >> 4;
    #pragma unroll
    for (int rr = 0; rr < 16; rr++) {
        int mr = ty * 16 + rr;
        int t = tgs[mr];
        int trow = (t < 64) ? t : 63;
        float corr = (t < 64) ? (wn * s0[mr * 64 + trow]) : 0.0f;
        float4 s0v = *(const float4*)&s0[mr * 64 + tx * 4];
        float cv[4];
        #pragma unroll
        for (int q = 0; q < 4; q++) {
            uint32_t co = SW128((uint32_t)((tx * 4 + q) * 128 + trow * 2));
            float ch = __bfloat162float(*(const __nv_bfloat16*)(sm + CH_OFF + co));
            float cl = __bfloat162float(*(const __nv_bfloat16*)(sm + CL_OFF + co));
            cv[q] = ch + cl;
        }
        float4 o;
        o.x = wn * s0v.x - cv[0] * corr;
        o.y = wn * s0v.y - cv[1] * corr;
        o.z = wn * s0v.z - cv[2] * corr;
        o.w = wn * s0v.w - cv[3] * corr;
        int nb = tx * 4;
        if (t == nb + 0) o.x = 0.0f;
        if (t == nb + 1) o.y = 0.0f;
        if (t == nb + 2) o.z = 0.0f;
        if (t == nb + 3) o.w = 0.0f;
        *(float4*)&out[SOFF + ((size_t)b * 512 + i0 + mr) * 64 + nb] = o;
    }
}

// ---- fused: logits epilogue + gumbel + 20x sinkhorn (log2) + greedy + backsub ----
__global__ void __launch_bounds__(256) k_sinkgreedy(const float* __restrict__ b3,
                                                    const float* __restrict__ gum,
                                                    float* __restrict__ out) {
    extern __shared__ float dsm[];
    float* m   = dsm;
    float* Lsh = dsm + 64 * 65;
    float* Msh = dsm + 2 * 64 * 65;
    __shared__ int colsh[64];
    int b = blockIdx.x, tid = threadIdx.x, lane = tid & 31, wd = tid >> 5;

    const float* Lg = out + LOFF + (size_t)b * 4096;
    for (int idx = tid; idx < 4096; idx += 256) {
        float x = g_part[(size_t)b * 4096 + idx] + b3[idx];
        x = tanhf(x * 0.1f) * 10.0f;
        float u = gum[(size_t)b * 4096 + idx];
        u = fmaxf(u, 1e-8f);
        float g = -__logf(-__logf(u));
        m[(idx >> 6) * 65 + (idx & 63)] = (x + g) * 7.213475204444817f;
        Lsh[(idx >> 6) * 65 + (idx & 63)] = Lg[idx];
    }
    __syncthreads();

    int r0 = wd * 8;
    float a[8], c[8], sm2[8];
    for (int it = 0; it < 20; it++) {
        #pragma unroll
        for (int q = 0; q < 8; q++) {
            a[q] = m[(r0 + q) * 65 + lane];
            c[q] = m[(r0 + q) * 65 + 32 + lane];
        }
        if (it == 0) {
            float mx[8];
            #pragma unroll
            for (int q = 0; q < 8; q++) mx[q] = fmaxf(a[q], c[q]);
            #pragma unroll
            for (int off = 16; off; off >>= 1)
                #pragma unroll
                for (int q = 0; q < 8; q++) mx[q] = fmaxf(mx[q], __shfl_xor_sync(~0u, mx[q], off));
            #pragma unroll
            for (int q = 0; q < 8; q++) sm2[q] = ex2f(a[q] - mx[q]) + ex2f(c[q] - mx[q]);
            #pragma unroll
            for (int off = 16; off; off >>= 1)
                #pragma unroll
                for (int q = 0; q < 8; q++) sm2[q] += __shfl_xor_sync(~0u, sm2[q], off);
            #pragma unroll
            for (int q = 0; q < 8; q++) {
                float lse = mx[q] + lg2f(sm2[q]);
                a[q] -= lse; c[q] -= lse;
            }
        } else {
            #pragma unroll
            for (int q = 0; q < 8; q++) sm2[q] = ex2f(a[q]) + ex2f(c[q]);
            #pragma unroll
            for (int off = 16; off; off >>= 1)
                #pragma unroll
                for (int q = 0; q < 8; q++) sm2[q] += __shfl_xor_sync(~0u, sm2[q], off);
            #pragma unroll
            for (int q = 0; q < 8; q++) {
                float lse = lg2f(sm2[q]);
                a[q] -= lse; c[q] -= lse;
            }
        }
        #pragma unroll
        for (int q = 0; q < 8; q++) {
            m[(r0 + q) * 65 + lane] = a[q];
            m[(r0 + q) * 65 + 32 + lane] = c[q];
        }
        __syncthreads();
        #pragma unroll
        for (int q = 0; q < 8; q++) {
            a[q] = m[lane * 65 + r0 + q];
            c[q] = m[(lane + 32) * 65 + r0 + q];
        }
        #pragma unroll
        for (int q = 0; q < 8; q++) sm2[q] = ex2f(a[q]) + ex2f(c[q]);
        #pragma unroll
        for (int off = 16; off; off >>= 1)
            #pragma unroll
            for (int q = 0; q < 8; q++) sm2[q] += __shfl_xor_sync(~0u, sm2[q], off);
        #pragma unroll
        for (int q = 0; q < 8; q++) {
            float lse = lg2f(sm2[q]);
            m[lane * 65 + r0 + q] = a[q] - lse;
            m[(lane + 32) * 65 + r0 + q] = c[q] - lse;
        }
        __syncthreads();
    }

    if (tid >= 224) {
        bool av0 = true, av1 = true;
        for (int i = 0; i < 64; i++) {
            float v0 = av0 ? m[i * 65 + lane] : -1e30f;
            float v1 = av1 ? m[i * 65 + 32 + lane] : -1e30f;
            float bv = v0; int bi = lane;
            if (v1 > v0) { bv = v1; bi = lane + 32; }
            #pragma unroll
            for (int off = 16; off; off >>= 1) {
                float ov = __shfl_xor_sync(~0u, bv, off);
                int   oi = __shfl_xor_sync(~0u, bi, off);
                if (ov > bv || (ov == bv && oi < bi)) { bv = ov; bi = oi; }
            }
            if (bi == lane) av0 = false;
            if (bi == lane + 32) av1 = false;
            if (lane == 0) colsh[i] = bi;
        }
    } else if (tid < 64) {
        int bc = tid;
        for (int aa = 63; aa >= 0; aa--) {
            float acc0 = (aa == bc) ? 1.0f : 0.0f, acc1 = 0.0f;
            int k = aa + 1;
            for (; k + 1 <= bc; k += 2) {
                acc0 += Lsh[k * 65 + aa] * Msh[k * 65 + bc];
                acc1 += Lsh[(k + 1) * 65 + aa] * Msh[(k + 1) * 65 + bc];
            }
            if (k <= bc) acc0 += Lsh[k * 65 + aa] * Msh[k * 65 + bc];
            Msh[aa * 65 + bc] = acc0 + acc1;
        }
    }
    __syncthreads();
    for (int idx = tid; idx < 4096; idx += 256) {
        int i = idx >> 6, l = idx & 63;
        out[POFF + (size_t)b * 4096 + idx] = (l == colsh[i]) ? 1.0f : 0.0f;
        out[WOFF + (size_t)b * 4096 + idx] = Lsh[colsh[i] * 65 + colsh[l]];
        float v = Msh[colsh[i] * 65 + colsh[l]];
        unsigned short hh, ll;
        split_bf16(v, hh, ll);
        *(unsigned short*)&g_Cthi[(size_t)b * 4096 + idx] = hh;
        *(unsigned short*)&g_Ctlo[(size_t)b * 4096 + idx] = ll;
    }
}

// ---------------- launch ----------------
extern "C" void kernel_launch(void* const* d_in, const int* in_sizes, int n_in,
                              void* d_out, int out_size) {
    const float* Lp  = (const float*)d_in[0];
    const float* eps = (const float*)d_in[1];
    const float* gum = (const float*)d_in[2];
    const float* z   = (const float*)d_in[3];
    const float* W1  = (const float*)d_in[4];
    const float* b1  = (const float*)d_in[5];
    const float* W2  = (const float*)d_in[6];
    const float* b2  = (const float*)d_in[7];
    const float* W3  = (const float*)d_in[8];
    const float* b3  = (const float*)d_in[9];
    const int*   tg  = (const int*)d_in[10];
    float* out = (float*)d_out;

    cudaFuncSetAttribute(k_sinkgreedy, cudaFuncAttributeMaxDynamicSharedMemorySize, 50176);
    cudaFuncSetAttribute(k_samples_mma, cudaFuncAttributeMaxDynamicSharedMemorySize, 81920);
    cudaFuncSetAttribute(k_logits_mma, cudaFuncAttributeMaxDynamicSharedMemorySize, 65536);

    k_cvt_z<<<32, 256>>>(z);                                          // 1
    k_prep<<<512, 256>>>(Lp, eps, out);                               // 2
    k_cvt_w3<<<dim3(64, 8), 256>>>(W3);                               // 3
    sgemm<<<dim3(8, 4, 16), 256>>>(0, W1, 512, 2017, 128, DDP, DDP);  // 4 <- profiled
    k_epi_gelu<<<1024, 256>>>(0, b1);                                 // 5
    sgemm<<<dim3(8, 4, 16), 256>>>(1, W2, 512, 512, 32, 512, 512);    // 6
    k_epi_gelu<<<1024, 256>>>(1, b2);                                 // 7
    k_logits_mma<<<dim3(32, 4), 256, 65536>>>();                      // 8
    k_sinkgreedy<<<512, 256, 49920>>>(b3, gum, out);                  // 9
    k_samples_mma<<<1024, 256, 81920>>>(tg, out);                     // 10
}

// round 15
// speedup vs baseline: 1.1690x; 1.0841x over previous
#include <cuda_runtime.h>
#include <cuda_bf16.h>
#include <cstdint>
#include <math.h>

// ---------------- problem constants ----------------
#define DIMN     64
#define L_DIM    2016
#define DD       2017
#define DDP      2032
#define BB       512
#define HID      512

#define POFF 0
#define LOFF 2097152
#define NOFF 4194304
#define WOFF 4227072
#define SOFF 6324224

typedef unsigned long long ull;

__device__ __forceinline__ ull pack2(float x, float y) {
    ull r; asm("mov.b64 %0,{%1,%2};" : "=l"(r) : "f"(x), "f"(y)); return r;
}
__device__ __forceinline__ void unpack2(ull v, float& x, float& y) {
    asm("mov.b64 {%0,%1},%2;" : "=f"(x), "=f"(y) : "l"(v));
}
__device__ __forceinline__ ull ffma2(ull a, ull b, ull c) {
    ull d; asm("fma.rn.f32x2 %0,%1,%2,%3;" : "=l"(d) : "l"(a), "l"(b), "l"(c)); return d;
}
__device__ __forceinline__ float ex2f(float x) {
    float y; asm("ex2.approx.f32 %0,%1;" : "=f"(y) : "f"(x)); return y;
}
__device__ __forceinline__ float lg2f(float x) {
    float y; asm("lg2.approx.f32 %0,%1;" : "=f"(y) : "f"(x)); return y;
}
__device__ __forceinline__ uint32_t smem_u32(const void* p) {
    uint32_t a;
    asm("{ .reg .u64 t; cvta.to.shared.u64 t, %1; cvt.u32.u64 %0, t; }" : "=r"(a) : "l"(p));
    return a;
}
#define SW128(o) ((o) ^ (((o) >> 3) & 0x70))

__device__ __forceinline__ void mma16816(float* c, const uint32_t* a, const uint32_t* b) {
    asm volatile(
        "mma.sync.aligned.m16n8k16.row.col.f32.bf16.bf16.f32 "
        "{%0,%1,%2,%3}, {%4,%5,%6,%7}, {%8,%9}, {%0,%1,%2,%3};"
        : "+f"(c[0]), "+f"(c[1]), "+f"(c[2]), "+f"(c[3])
        : "r"(a[0]), "r"(a[1]), "r"(a[2]), "r"(a[3]), "r"(b[0]), "r"(b[1]));
}
__device__ __forceinline__ void ldsm_x4(uint32_t* r, uint32_t addr) {
    asm volatile("ldmatrix.sync.aligned.m8n8.x4.shared.b16 {%0,%1,%2,%3}, [%4];"
                 : "=r"(r[0]), "=r"(r[1]), "=r"(r[2]), "=r"(r[3]) : "r"(addr));
}
__device__ __forceinline__ void ldsm_x2(uint32_t* r, uint32_t addr) {
    asm volatile("ldmatrix.sync.aligned.m8n8.x2.shared.b16 {%0,%1}, [%2];"
                 : "=r"(r[0]), "=r"(r[1]) : "r"(addr));
}
__device__ __forceinline__ void split_bf16(float x, unsigned short& h, unsigned short& l) {
    __nv_bfloat16 hb = __float2bfloat16_rn(x);
    float r = x - __bfloat162float(hb);
    __nv_bfloat16 lb = __float2bfloat16_rn(r);
    h = __bfloat16_as_ushort(hb);
    l = __bfloat16_as_ushort(lb);
}

// ---------------- device scratch ----------------
__device__ float g_flb[BB * DDP];
__device__ float g_part[16 * 262144];
__device__ float g_h1[BB * HID];
__device__ float g_wnoise[BB];
__device__ __nv_bfloat16 g_h2hi[BB * HID], g_h2lo[BB * HID];
__device__ __nv_bfloat16 g_Bhi[4096 * 512], g_Blo[4096 * 512];    // W3^T split [n][k]
__device__ __nv_bfloat16 g_zhi[512 * 64], g_zlo[512 * 64];
__device__ __nv_bfloat16 g_Cthi[BB * 4096], g_Ctlo[BB * 4096];    // B[n][j]=M[c_n][c_j]

// ---------------- kernel: full_l_batch (padded), noises, L ----------------
__global__ void k_prep(const float* __restrict__ Lp, const float* __restrict__ epsL,
                       float* __restrict__ out) {
    int b = blockIdx.x, tid = threadIdx.x;
    __shared__ float flb[DD];
    for (int d = tid; d < DDP; d += 256) {
        float v = 0.0f;
        if (d < DD) {
            float mean = Lp[d];
            float raw  = Lp[DD + d];
            v = mean + expf(tanhf(raw * 0.1f) * 10.0f) * epsL[(size_t)b * DD + d];
            flb[d] = v;
        }
        g_flb[(size_t)b * DDP + d] = v;
    }
    __syncthreads();
    if (tid == 0) g_wnoise[b] = flb[L_DIM];
    if (tid < DIMN) out[NOFF + b * DIMN + tid] = flb[L_DIM];
    for (int idx = tid; idx < 4096; idx += 256) {
        int jr = idx >> 6, ic = idx & 63;
        float v = 0.0f;
        if (ic < jr) v = flb[ic * 63 - (ic * (ic - 1)) / 2 + (jr - ic - 1)];
        out[LOFF + (size_t)b * 4096 + idx] = v;
    }
}

// ---- fp32 SGEMM (FFMA2), 128x64 tile, BK=16, split-K ----
__global__ void __launch_bounds__(256) sgemm(int which, const float* __restrict__ Bm,
                                             int N, int Kb, int kChunk, int lda, int KpadT) {
    const float* __restrict__ A = (which == 0) ? g_flb : g_h1;
    int n0 = blockIdx.x * 64, m0 = blockIdx.y * 128, s = blockIdx.z;
    int k0 = s * kChunk;
    int k1 = min(KpadT, k0 + kChunk);
    __shared__ __align__(16) float As[16][132];
    __shared__ __align__(16) float Bs[16][64];
    int tid = threadIdx.x, tx = tid & 15, ty = tid >> 4;
    ull acc2[4][4];
    #pragma unroll
    for (int p = 0; p < 4; p++)
        #pragma unroll
        for (int j = 0; j < 4; j++) acc2[p][j] = 0ull;

    int ar0 = tid >> 2, ak = (tid & 3) * 4;
    int bk = tid >> 4, bn = (tid & 15) * 4;

    float4 pa0, pa1, pb;
    auto fetch = [&](int kb) {
        int kk = kb + ak;
        pa0 = *(const float4*)&A[(size_t)(m0 + ar0) * lda + kk];
        pa1 = *(const float4*)&A[(size_t)(m0 + ar0 + 64) * lda + kk];
        pb = make_float4(0.f, 0.f, 0.f, 0.f);
        if (kb + bk < Kb) pb = *(const float4*)&Bm[(size_t)(kb + bk) * N + n0 + bn];
    };

    fetch(k0);
    for (int kb = k0; kb < k1; kb += 16) {
        As[ak + 0][ar0] = pa0.x; As[ak + 1][ar0] = pa0.y;
        As[ak + 2][ar0] = pa0.z; As[ak + 3][ar0] = pa0.w;
        As[ak + 0][ar0 + 64] = pa1.x; As[ak + 1][ar0 + 64] = pa1.y;
        As[ak + 2][ar0 + 64] = pa1.z; As[ak + 3][ar0 + 64] = pa1.w;
        *(float4*)&Bs[bk][bn] = pb;
        __syncthreads();
        if (kb + 16 < k1) fetch(kb + 16);
        #pragma unroll
        for (int kk = 0; kk < 16; kk++) {
            ulonglong2 aA = *(const ulonglong2*)&As[kk][ty * 8];
            ulonglong2 aB = *(const ulonglong2*)&As[kk][ty * 8 + 4];
            float4 b = *(const float4*)&Bs[kk][tx * 4];
            ull bp0 = pack2(b.x, b.x), bp1 = pack2(b.y, b.y);
            ull bp2 = pack2(b.z, b.z), bp3 = pack2(b.w, b.w);
            acc2[0][0] = ffma2(aA.x, bp0, acc2[0][0]);
            acc2[0][1] = ffma2(aA.x, bp1, acc2[0][1]);
            acc2[0][2] = ffma2(aA.x, bp2, acc2[0][2]);
            acc2[0][3] = ffma2(aA.x, bp3, acc2[0][3]);
            acc2[1][0] = ffma2(aA.y, bp0, acc2[1][0]);
            acc2[1][1] = ffma2(aA.y, bp1, acc2[1][1]);
            acc2[1][2] = ffma2(aA.y, bp2, acc2[1][2]);
            acc2[1][3] = ffma2(aA.y, bp3, acc2[1][3]);
            acc2[2][0] = ffma2(aB.x, bp0, acc2[2][0]);
            acc2[2][1] = ffma2(aB.x, bp1, acc2[2][1]);
            acc2[2][2] = ffma2(aB.x, bp2, acc2[2][2]);
            acc2[2][3] = ffma2(aB.x, bp3, acc2[2][3]);
            acc2[3][0] = ffma2(aB.y, bp0, acc2[3][0]);
            acc2[3][1] = ffma2(aB.y, bp1, acc2[3][1]);
            acc2[3][2] = ffma2(aB.y, bp2, acc2[3][2]);
            acc2[3][3] = ffma2(aB.y, bp3, acc2[3][3]);
        }
        __syncthreads();
    }
    size_t MN = (size_t)512 * N;
    float* dst = &g_part[(size_t)s * MN];
    #pragma unroll
    for (int p = 0; p < 4; p++) {
        float lo[4], hi[4];
        #pragma unroll
        for (int j = 0; j < 4; j++) unpack2(acc2[p][j], lo[j], hi[j]);
        int m = m0 + ty * 8 + 2 * p;
        *(float4*)&dst[(size_t)m * N + n0 + tx * 4] = make_float4(lo[0], lo[1], lo[2], lo[3]);
        *(float4*)&dst[(size_t)(m + 1) * N + n0 + tx * 4] = make_float4(hi[0], hi[1], hi[2], hi[3]);
    }
}

// ---------------- epilogue: sum 16 partials + bias + gelu ----------------
__global__ void k_epi_gelu(int dst, const float* __restrict__ bias) {
    int idx = blockIdx.x * 256 + threadIdx.x;
    float x = bias[idx & 511];
    #pragma unroll
    for (int s = 0; s < 16; s++) x += g_part[s * 262144 + idx];
    float x3 = x * x * x;
    float t = tanhf(0.7978845608028654f * (x + 0.044715f * x3));
    float v = 0.5f * x * (1.0f + t);
    if (dst == 0) {
        g_h1[idx] = v;
    } else {
        unsigned short h, l;
        split_bf16(v, h, l);
        *(unsigned short*)&g_h2hi[idx] = h;
        *(unsigned short*)&g_h2lo[idx] = l;
    }
}

// ---- z -> bf16 hi/lo ----
__global__ void k_cvt_z(const float* __restrict__ z) {
    int i = (blockIdx.x * 256 + threadIdx.x) * 4;
    float4 x = *(const float4*)&z[i];
    unsigned short h0, h1, h2v, h3, l0, l1, l2, l3;
    split_bf16(x.x, h0, l0); split_bf16(x.y, h1, l1);
    split_bf16(x.z, h2v, l2); split_bf16(x.w, h3, l3);
    *(uint2*)&g_zhi[i] = make_uint2((uint32_t)h1 << 16 | h0, (uint32_t)h3 << 16 | h2v);
    *(uint2*)&g_zlo[i] = make_uint2((uint32_t)l1 << 16 | l0, (uint32_t)l3 << 16 | l2);
}

// ---- W3[k][n] -> g_Bhi/lo [n][k] bf16 split ----
__global__ void __launch_bounds__(256) k_cvt_w3(const float* __restrict__ W3) {
    int n0 = blockIdx.x * 64, k0 = blockIdx.y * 64, tid = threadIdx.x;
    __shared__ float t[64][65];
    #pragma unroll
    for (int i = 0; i < 16; i++) {
        int slot = tid + i * 256;
        int r = slot >> 6, c = slot & 63;
        t[r][c] = W3[(size_t)(k0 + r) * 4096 + n0 + c];
    }
    __syncthreads();
    #pragma unroll
    for (int i = 0; i < 8; i++) {
        int slot = tid + i * 256;
        int r2 = slot >> 5, j = slot & 31;
        unsigned short ha, hb, la, lb;
        split_bf16(t[2 * j][r2], ha, la);
        split_bf16(t[2 * j + 1][r2], hb, lb);
        size_t o = (size_t)(n0 + r2) * 512 + k0 + 2 * j;
        *(uint32_t*)&g_Bhi[o] = (uint32_t)hb << 16 | ha;
        *(uint32_t*)&g_Blo[o] = (uint32_t)lb << 16 | la;
    }
}

// ---- logits via mma.sync: D[512,4096] = h2 @ W3, 3-term bf16 split (proven) ----
#define LA_H 0
#define LA_L 16384
#define LB_H 32768
#define LB_L 49152

__global__ void __launch_bounds__(256) k_logits_mma() {
    extern __shared__ char sm[];
    uint32_t sb = smem_u32(sm);
    int tid = threadIdx.x, w = tid >> 5, lane = tid & 31;
    int n0 = blockIdx.x * 128, m0 = blockIdx.y * 128;
    int wm = (w & 3) * 32, wn = (w >> 2) * 64;

    float acc[2][8][4];
    #pragma unroll
    for (int mt = 0; mt < 2; mt++)
        #pragma unroll
        for (int j = 0; j < 8; j++)
            #pragma unroll
            for (int q = 0; q < 4; q++) acc[mt][j][q] = 0.0f;

    int arow = lane & 15, akq = (lane >> 4) * 8;
    int brow = lane & 7, bkq = ((lane >> 3) & 1) * 8;

    for (int c = 0; c < 8; c++) {
        for (int s = tid; s < 1024; s += 256) {
            int r = s >> 3, q = s & 7;
            uint32_t so = SW128((uint32_t)(r * 128 + q * 16));
            size_t ga = (size_t)(m0 + r) * 512 + c * 64 + q * 8;
            size_t gb = (size_t)(n0 + r) * 512 + c * 64 + q * 8;
            *(uint4*)(sm + LA_H + so) = *(const uint4*)&g_h2hi[ga];
            *(uint4*)(sm + LA_L + so) = *(const uint4*)&g_h2lo[ga];
            *(uint4*)(sm + LB_H + so) = *(const uint4*)&g_Bhi[gb];
            *(uint4*)(sm + LB_L + so) = *(const uint4*)&g_Blo[gb];
        }
        __syncthreads();
        #pragma unroll
        for (int ks = 0; ks < 4; ks++) {
            uint32_t ah[2][4], al[2][4];
            #pragma unroll
            for (int mt = 0; mt < 2; mt++) {
                uint32_t ao = SW128((uint32_t)((wm + mt * 16 + arow) * 128
                                               + (ks * 16 + akq) * 2));
                ldsm_x4(ah[mt], sb + LA_H + ao);
                ldsm_x4(al[mt], sb + LA_L + ao);
            }
            #pragma unroll
            for (int j = 0; j < 8; j++) {
                uint32_t bh[2], bl[2];
                uint32_t bo = SW128((uint32_t)((wn + j * 8 + brow) * 128
                                               + (ks * 16 + bkq) * 2));
                ldsm_x2(bh, sb + LB_H + bo);
                ldsm_x2(bl, sb + LB_L + bo);
                #pragma unroll
                for (int mt = 0; mt < 2; mt++) {
                    mma16816(acc[mt][j], ah[mt], bh);
                    mma16816(acc[mt][j], ah[mt], bl);
                    mma16816(acc[mt][j], al[mt], bh);
                }
            }
        }
        __syncthreads();
    }
    #pragma unroll
    for (int mt = 0; mt < 2; mt++)
        #pragma unroll
        for (int j = 0; j < 8; j++) {
            int r = m0 + wm + mt * 16 + (lane >> 2);
            int cc = n0 + wn + j * 8 + (lane & 3) * 2;
            *(float2*)&g_part[(size_t)r * 4096 + cc] = make_float2(acc[mt][j][0], acc[mt][j][1]);
            *(float2*)&g_part[(size_t)(r + 8) * 4096 + cc] = make_float2(acc[mt][j][2], acc[mt][j][3]);
        }
}

// ---- samples v4: 128-row tiles, register-fragment Sherman-Morrison epilogue ----
#define ZH_OFF 0
#define ZL_OFF 16384
#define CH_OFF 32768
#define CL_OFF 40960

__global__ void __launch_bounds__(256) k_samples_mma(const int* __restrict__ tg,
                                                     float* __restrict__ out) {
    extern __shared__ char sm[];
    uint32_t sb = smem_u32(sm);
    __shared__ int tgs[128];
    __shared__ float wsh;
    int blk = blockIdx.x, b = blk >> 2, i0 = (blk & 3) * 128;
    int tid = threadIdx.x, w = tid >> 5, lane = tid & 31;

    for (int slot = tid; slot < 1024; slot += 256) {
        int r = slot >> 3, q = slot & 7;
        uint32_t so = SW128((uint32_t)(r * 128 + q * 16));
        *(uint4*)(sm + ZH_OFF + so) = *(const uint4*)&g_zhi[(size_t)(i0 + r) * 64 + q * 8];
        *(uint4*)(sm + ZL_OFF + so) = *(const uint4*)&g_zlo[(size_t)(i0 + r) * 64 + q * 8];
    }
    for (int slot = tid; slot < 512; slot += 256) {
        int r = slot >> 3, q = slot & 7;
        uint32_t so = SW128((uint32_t)(r * 128 + q * 16));
        *(uint4*)(sm + CH_OFF + so) = *(const uint4*)&g_Cthi[(size_t)b * 4096 + r * 64 + q * 8];
        *(uint4*)(sm + CL_OFF + so) = *(const uint4*)&g_Ctlo[(size_t)b * 4096 + r * 64 + q * 8];
    }
    if (tid < 128) tgs[tid] = tg[i0 + tid];
    if (tid == 0) wsh = g_wnoise[b];
    __syncthreads();

    float acc[8][4];
    #pragma unroll
    for (int j = 0; j < 8; j++)
        #pragma unroll
        for (int q = 0; q < 4; q++) acc[j][q] = 0.0f;

    int wm = w * 16;
    int arow = lane & 15, akq = (lane >> 4) * 8;
    int brow = lane & 7, bkq = ((lane >> 3) & 1) * 8;

    #pragma unroll
    for (int ks = 0; ks < 4; ks++) {
        uint32_t ah[4], al[4];
        uint32_t ao = SW128((uint32_t)((wm + arow) * 128 + (ks * 16 + akq) * 2));
        ldsm_x4(ah, sb + ZH_OFF + ao);
        ldsm_x4(al, sb + ZL_OFF + ao);
        #pragma unroll
        for (int j = 0; j < 8; j++) {
            uint32_t bh[2], bl[2];
            uint32_t bo = SW128((uint32_t)((j * 8 + brow) * 128 + (ks * 16 + bkq) * 2));
            ldsm_x2(bh, sb + CH_OFF + bo);
            ldsm_x2(bl, sb + CL_OFF + bo);
            mma16816(acc[j], ah, bh);
            mma16816(acc[j], ah, bl);
            mma16816(acc[j], al, bh);
        }
    }

    // register-fragment epilogue: thread owns rows r0 = wm + (lane>>2) and r0+8,
    // cols j*8 + (lane&3)*2 + {0,1}
    float wn = wsh;
    int qc = lane & 3;
    #pragma unroll
    for (int rr = 0; rr < 2; rr++) {
        int row = wm + (lane >> 2) + rr * 8;
        int t = tgs[row];
        int trow = (t < 64) ? t : 63;
        int jt = trow >> 3, within = trow & 7;
        // extract s0[row][trow] from the quad's fragments
        float cand = 0.0f;
        if (qc == (within >> 1)) {
            #pragma unroll
            for (int j = 0; j < 8; j++)
                if (j == jt) cand = acc[j][rr * 2 + (within & 1)];
        }
        cand += __shfl_xor_sync(~0u, cand, 1);
        cand += __shfl_xor_sync(~0u, cand, 2);
        float corr = (t < 64) ? (wn * cand) : 0.0f;

        float* orow = &out[SOFF + ((size_t)b * 512 + i0 + row) * 64];
        #pragma unroll
        for (int j = 0; j < 8; j++) {
            int c0 = j * 8 + qc * 2;
            float cva, cvb;
            {
                uint32_t coa = SW128((uint32_t)(c0 * 128 + trow * 2));
                uint32_t cob = SW128((uint32_t)((c0 + 1) * 128 + trow * 2));
                cva = __bfloat162float(*(const __nv_bfloat16*)(sm + CH_OFF + coa))
                    + __bfloat162float(*(const __nv_bfloat16*)(sm + CL_OFF + coa));
                cvb = __bfloat162float(*(const __nv_bfloat16*)(sm + CH_OFF + cob))
                    + __bfloat162float(*(const __nv_bfloat16*)(sm + CL_OFF + cob));
            }
            float2 o;
            o.x = wn * acc[j][rr * 2 + 0] - cva * corr;
            o.y = wn * acc[j][rr * 2 + 1] - cvb * corr;
            if (t == c0) o.x = 0.0f;
            if (t == c0 + 1) o.y = 0.0f;
            *(float2*)&orow[c0] = o;
        }
    }
}

// ---- fused: logits epilogue + gumbel + 20x sinkhorn (log2) + greedy + backsub ----
__global__ void __launch_bounds__(256) k_sinkgreedy(const float* __restrict__ b3,
                                                    const float* __restrict__ gum,
                                                    float* __restrict__ out) {
    extern __shared__ float dsm[];
    float* m   = dsm;
    float* Lsh = dsm + 64 * 65;
    float* Msh = dsm + 2 * 64 * 65;
    __shared__ int colsh[64];
    int b = blockIdx.x, tid = threadIdx.x, lane = tid & 31, wd = tid >> 5;

    const float* Lg = out + LOFF + (size_t)b * 4096;
    for (int idx = tid; idx < 4096; idx += 256) {
        float x = g_part[(size_t)b * 4096 + idx] + b3[idx];
        x = tanhf(x * 0.1f) * 10.0f;
        float u = gum[(size_t)b * 4096 + idx];
        u = fmaxf(u, 1e-8f);
        float g = -__logf(-__logf(u));
        m[(idx >> 6) * 65 + (idx & 63)] = (x + g) * 7.213475204444817f;
        Lsh[(idx >> 6) * 65 + (idx & 63)] = Lg[idx];
    }
    __syncthreads();

    int r0 = wd * 8;
    float a[8], c[8], sm2[8];
    for (int it = 0; it < 20; it++) {
        #pragma unroll
        for (int q = 0; q < 8; q++) {
            a[q] = m[(r0 + q) * 65 + lane];
            c[q] = m[(r0 + q) * 65 + 32 + lane];
        }
        if (it == 0) {
            float mx[8];
            #pragma unroll
            for (int q = 0; q < 8; q++) mx[q] = fmaxf(a[q], c[q]);
            #pragma unroll
            for (int off = 16; off; off >>= 1)
                #pragma unroll
                for (int q = 0; q < 8; q++) mx[q] = fmaxf(mx[q], __shfl_xor_sync(~0u, mx[q], off));
            #pragma unroll
            for (int q = 0; q < 8; q++) sm2[q] = ex2f(a[q] - mx[q]) + ex2f(c[q] - mx[q]);
            #pragma unroll
            for (int off = 16; off; off >>= 1)
                #pragma unroll
                for (int q = 0; q < 8; q++) sm2[q] += __shfl_xor_sync(~0u, sm2[q], off);
            #pragma unroll
            for (int q = 0; q < 8; q++) {
                float lse = mx[q] + lg2f(sm2[q]);
                a[q] -= lse; c[q] -= lse;
            }
        } else {
            #pragma unroll
            for (int q = 0; q < 8; q++) sm2[q] = ex2f(a[q]) + ex2f(c[q]);
            #pragma unroll
            for (int off = 16; off; off >>= 1)
                #pragma unroll
                for (int q = 0; q < 8; q++) sm2[q] += __shfl_xor_sync(~0u, sm2[q], off);
            #pragma unroll
            for (int q = 0; q < 8; q++) {
                float lse = lg2f(sm2[q]);
                a[q] -= lse; c[q] -= lse;
            }
        }
        #pragma unroll
        for (int q = 0; q < 8; q++) {
            m[(r0 + q) * 65 + lane] = a[q];
            m[(r0 + q) * 65 + 32 + lane] = c[q];
        }
        __syncthreads();
        #pragma unroll
        for (int q = 0; q < 8; q++) {
            a[q] = m[lane * 65 + r0 + q];
            c[q] = m[(lane + 32) * 65 + r0 + q];
        }
        #pragma unroll
        for (int q = 0; q < 8; q++) sm2[q] = ex2f(a[q]) + ex2f(c[q]);
        #pragma unroll
        for (int off = 16; off; off >>= 1)
            #pragma unroll
            for (int q = 0; q < 8; q++) sm2[q] += __shfl_xor_sync(~0u, sm2[q], off);
        #pragma unroll
        for (int q = 0; q < 8; q++) {
            float lse = lg2f(sm2[q]);
            m[lane * 65 + r0 + q] = a[q] - lse;
            m[(lane + 32) * 65 + r0 + q] = c[q] - lse;
        }
        __syncthreads();
    }

    if (tid >= 224) {
        bool av0 = true, av1 = true;
        for (int i = 0; i < 64; i++) {
            float v0 = av0 ? m[i * 65 + lane] : -1e30f;
            float v1 = av1 ? m[i * 65 + 32 + lane] : -1e30f;
            float bv = v0; int bi = lane;
            if (v1 > v0) { bv = v1; bi = lane + 32; }
            #pragma unroll
            for (int off = 16; off; off >>= 1) {
                float ov = __shfl_xor_sync(~0u, bv, off);
                int   oi = __shfl_xor_sync(~0u, bi, off);
                if (ov > bv || (ov == bv && oi < bi)) { bv = ov; bi = oi; }
            }
            if (bi == lane) av0 = false;
            if (bi == lane + 32) av1 = false;
            if (lane == 0) colsh[i] = bi;
        }
    } else if (tid < 64) {
        int bc = tid;
        for (int aa = 63; aa >= 0; aa--) {
            float acc0 = (aa == bc) ? 1.0f : 0.0f, acc1 = 0.0f;
            int k = aa + 1;
            for (; k + 1 <= bc; k += 2) {
                acc0 += Lsh[k * 65 + aa] * Msh[k * 65 + bc];
                acc1 += Lsh[(k + 1) * 65 + aa] * Msh[(k + 1) * 65 + bc];
            }
            if (k <= bc) acc0 += Lsh[k * 65 + aa] * Msh[k * 65 + bc];
            Msh[aa * 65 + bc] = acc0 + acc1;
        }
    }
    __syncthreads();
    for (int idx = tid; idx < 4096; idx += 256) {
        int i = idx >> 6, l = idx & 63;
        out[POFF + (size_t)b * 4096 + idx] = (l == colsh[i]) ? 1.0f : 0.0f;
        out[WOFF + (size_t)b * 4096 + idx] = Lsh[colsh[i] * 65 + colsh[l]];
        float v = Msh[colsh[i] * 65 + colsh[l]];
        unsigned short hh, ll;
        split_bf16(v, hh, ll);
        *(unsigned short*)&g_Cthi[(size_t)b * 4096 + idx] = hh;
        *(unsigned short*)&g_Ctlo[(size_t)b * 4096 + idx] = ll;
    }
}

// ---------------- launch ----------------
extern "C" void kernel_launch(void* const* d_in, const int* in_sizes, int n_in,
                              void* d_out, int out_size) {
    const float* Lp  = (const float*)d_in[0];
    const float* eps = (const float*)d_in[1];
    const float* gum = (const float*)d_in[2];
    const float* z   = (const float*)d_in[3];
    const float* W1  = (const float*)d_in[4];
    const float* b1  = (const float*)d_in[5];
    const float* W2  = (const float*)d_in[6];
    const float* b2  = (const float*)d_in[7];
    const float* W3  = (const float*)d_in[8];
    const float* b3  = (const float*)d_in[9];
    const int*   tg  = (const int*)d_in[10];
    float* out = (float*)d_out;

    cudaFuncSetAttribute(k_sinkgreedy, cudaFuncAttributeMaxDynamicSharedMemorySize, 50176);
    cudaFuncSetAttribute(k_samples_mma, cudaFuncAttributeMaxDynamicSharedMemorySize, 49152);
    cudaFuncSetAttribute(k_logits_mma, cudaFuncAttributeMaxDynamicSharedMemorySize, 65536);

    k_cvt_z<<<32, 256>>>(z);                                          // 1
    k_prep<<<512, 256>>>(Lp, eps, out);                               // 2
    k_cvt_w3<<<dim3(64, 8), 256>>>(W3);                               // 3
    sgemm<<<dim3(8, 4, 16), 256>>>(0, W1, 512, 2017, 128, DDP, DDP);  // 4 <- profiled
    k_epi_gelu<<<1024, 256>>>(0, b1);                                 // 5
    sgemm<<<dim3(8, 4, 16), 256>>>(1, W2, 512, 512, 32, 512, 512);    // 6
    k_epi_gelu<<<1024, 256>>>(1, b2);                                 // 7
    k_logits_mma<<<dim3(32, 4), 256, 65536>>>();                      // 8
    k_sinkgreedy<<<512, 256, 49920>>>(b3, gum, out);                  // 9
    k_samples_mma<<<2048, 256, 49152>>>(tg, out);                     // 10
}